// round 14
// baseline (speedup 1.0000x reference)
#include <cuda_runtime.h>
#include <cuda_fp16.h>
#include <cstdint>

#define BATCH 4
#define CH    128
#define HH    128
#define WW    128
#define KPT   8
#define HWSZ  (HH * WW)           // 16384
#define NPIX  (BATCH * HWSZ)      // 65536
#define RADIUS 4.0f
#define SCALE 0.08838834764831845f  // C^-0.5

// Scratch buffers (pixel-major / NHWC, fp16)
__device__ __half g_xh [NPIX * CH];   // x fp16 NHWC (gather + GEMM operand)
__device__ __half g_uh [NPIX * CH];   // u = (SCALE*GT) @ x
__device__ __half g_yh [NPIX * CH];   // y~ = sum_k attn * x~
__device__ __half g_gth [CH * CH];    // GT[d][c] * SCALE, K-contig
__device__ __half g_wpvh[CH * CH];    // W_pv[o][c], K-contig

// ---------------- helpers ----------------
__device__ __forceinline__ uint32_t smem_u32(const void* p) {
    uint32_t a;
    asm("{ .reg .u64 t; cvta.to.shared.u64 t, %1; cvt.u32.u64 %0, t; }"
        : "=r"(a) : "l"(p));
    return a;
}
__device__ __forceinline__ unsigned h2u(__half2 h) { return *reinterpret_cast<unsigned*>(&h); }
__device__ __forceinline__ __half2 u2h(unsigned u) { return *reinterpret_cast<__half2*>(&u); }

__device__ __forceinline__ void ldsm_x4(uint32_t a, uint32_t& r0, uint32_t& r1,
                                        uint32_t& r2, uint32_t& r3) {
    asm volatile("ldmatrix.sync.aligned.m8n8.x4.shared.b16 {%0,%1,%2,%3}, [%4];"
                 : "=r"(r0), "=r"(r1), "=r"(r2), "=r"(r3) : "r"(a));
}
__device__ __forceinline__ void ldsm_x4_t(uint32_t a, uint32_t& r0, uint32_t& r1,
                                          uint32_t& r2, uint32_t& r3) {
    asm volatile("ldmatrix.sync.aligned.m8n8.x4.trans.shared.b16 {%0,%1,%2,%3}, [%4];"
                 : "=r"(r0), "=r"(r1), "=r"(r2), "=r"(r3) : "r"(a));
}
__device__ __forceinline__ void mma16816(float* d, uint32_t a0, uint32_t a1,
                                         uint32_t a2, uint32_t a3,
                                         uint32_t b0, uint32_t b1) {
    asm volatile("mma.sync.aligned.m16n8k16.row.col.f32.f16.f16.f32 "
                 "{%0,%1,%2,%3},{%4,%5,%6,%7},{%8,%9},{%0,%1,%2,%3};"
                 : "+f"(d[0]), "+f"(d[1]), "+f"(d[2]), "+f"(d[3])
                 : "r"(a0), "r"(a1), "r"(a2), "r"(a3), "r"(b0), "r"(b1));
}

// copy an Rx128 fp16 K-contig tile (256B rows) into XOR-swizzled smem
template <int ROWS>
__device__ __forceinline__ void load_tile(const __half* __restrict__ src,
                                          char* dst, int tid) {
#pragma unroll
    for (int i = 0; i < ROWS / 16; i++) {
        int idx = i * 256 + tid;           // chunks of 16B
        int r   = idx >> 4;
        int c   = idx & 15;
        uint4 v = *(const uint4*)(src + (size_t)r * 128 + c * 8);
        *(uint4*)(dst + r * 256 + ((c ^ (r & 7)) << 4)) = v;
    }
}

// ---------------- Kernel 0: weight fold (coalesced streaming version) -------
// 32 blocks: 0..15 -> GT slices (8 d each), 16..31 -> W_pv slices (8 o each).
__global__ void __launch_bounds__(256) k_wall(const float* __restrict__ wqkv,
                                              const float* __restrict__ wproj) {
    __shared__ float sw[1024];
    const int blk = blockIdx.x;
    const int tid = threadIdx.x;
    const int c   = tid & 127;
    const int hf  = tid >> 7;

    if (blk < 16) {
        const int d0 = blk * 8;
        // stage Wk[o][d0..d0+7] (coalesced 8-wide)
#pragma unroll
        for (int i = 0; i < 4; i++) {
            int idx = i * 256 + tid;
            int o = idx >> 3, dl = idx & 7;
            sw[o * 8 + dl] = wqkv[(128 + o) * CH + d0 + dl];
        }
        __syncthreads();
        float acc[4] = {0.f, 0.f, 0.f, 0.f};
#pragma unroll 4
        for (int o = 0; o < 128; o++) {
            float w = wqkv[o * CH + c];               // coalesced stream
#pragma unroll
            for (int j = 0; j < 4; j++)
                acc[j] += w * sw[o * 8 + hf * 4 + j]; // smem broadcast
        }
#pragma unroll
        for (int j = 0; j < 4; j++)
            g_gth[(d0 + hf * 4 + j) * CH + c] = __float2half(acc[j] * SCALE);
    } else {
        const int o0 = (blk - 16) * 8;
        // stage Wproj[o0..o0+7][m] (coalesced)
#pragma unroll
        for (int i = 0; i < 4; i++) {
            int idx = i * 256 + tid;
            int r = idx >> 7, m = idx & 127;
            sw[r * 128 + m] = wproj[(o0 + r) * CH + m];
        }
        __syncthreads();
        float acc[4] = {0.f, 0.f, 0.f, 0.f};
#pragma unroll 4
        for (int m = 0; m < 128; m++) {
            float v = wqkv[(256 + m) * CH + c];       // coalesced stream
#pragma unroll
            for (int j = 0; j < 4; j++)
                acc[j] += sw[(hf * 4 + j) * 128 + m] * v;
        }
#pragma unroll
        for (int j = 0; j < 4; j++)
            g_wpvh[(o0 + hf * 4 + j) * CH + c] = __float2half(acc[j]);
    }
}

// ---------------- Kernel 1 (fused): x NCHW -> A operand (=xh) -> u GEMM -----
// smem: A operand [0,16K) | GT [16K,48K) | staging S [48K, 48K+18432)
#define SST 72   // staging stride in halfs (144B: conflict-free ldmatrix rows)
__global__ void __launch_bounds__(256) k_prep_u(const float* __restrict__ x) {
    extern __shared__ __align__(128) char sm[];
    const int tid  = threadIdx.x;
    const int lane = tid & 31, wid = tid >> 5;
    const int wm = wid & 1, wn = wid >> 1;
    const int pix0 = blockIdx.x << 6;
    const int b    = pix0 >> 14;
    const int hw0  = pix0 & (HWSZ - 1);

    load_tile<128>(g_gth, sm + 16384, tid);                // GT (32KB)

    __half* S = (__half*)(sm + 49152);

    // Phase 1: coalesced stage
#pragma unroll
    for (int i = 0; i < 8; i++) {
        int idx = i * 256 + tid;
        int c = idx >> 4, j4 = idx & 15;
        float4 v = *(const float4*)(x + ((size_t)b * CH + c) * HWSZ + hw0 + j4 * 4);
        *(__half2*)(S + c * SST + j4 * 4)     = __floats2half2_rn(v.x, v.y);
        *(__half2*)(S + c * SST + j4 * 4 + 2) = __floats2half2_rn(v.z, v.w);
    }
    __syncthreads();

    // Phase 1c: hardware transpose into swizzled A operand
#pragma unroll
    for (int i = 0; i < 4; i++) {
        int g  = wid + 8 * i;              // tile group 0..31
        int c0 = (g >> 3) << 5;            // 32-channel span
        int pb = g & 7;                    // px block (8 px)
        uint32_t src = smem_u32(S + (c0 + ((lane >> 3) << 3) + (lane & 7)) * SST + pb * 8);
        uint32_t r0, r1, r2, r3;
        ldsm_x4_t(src, r0, r1, r2, r3);
        int px = (pb << 3) + (lane >> 2);
        uint32_t rr[4] = {r0, r1, r2, r3};
#pragma unroll
        for (int k = 0; k < 4; k++) {
            int c2    = (c0 >> 1) + (k << 2) + (lane & 3);
            int chunk = c2 >> 2;
            int inner = (c2 & 3) << 2;
            *(uint32_t*)(sm + px * 256 + ((chunk ^ (px & 7)) << 4) + inner) = rr[k];
        }
    }
    __syncthreads();

    // Phase 1b: write g_xh NHWC from the swizzled operand
#pragma unroll
    for (int i = 0; i < 4; i++) {
        int idx = i * 256 + tid;
        int px = idx >> 4, q = idx & 15;
        uint4 v = *(const uint4*)(sm + px * 256 + ((q ^ (px & 7)) << 4));
        *(uint4*)(g_xh + (size_t)(pix0 + px) * CH + q * 8) = v;
    }

    // Phase 2: u = A @ GT^T  (M=64px, N=128dch)
    float acc[2][4][4];
#pragma unroll
    for (int i = 0; i < 2; i++)
#pragma unroll
        for (int j = 0; j < 4; j++)
#pragma unroll
            for (int k = 0; k < 4; k++) acc[i][j][k] = 0.f;

    const uint32_t smA = smem_u32(sm);
    const uint32_t smB = smA + 16384;

#pragma unroll
    for (int ks = 0; ks < 8; ks++) {
        uint32_t a[2][4];
#pragma unroll
        for (int mi = 0; mi < 2; mi++) {
            int row = wm * 32 + mi * 16 + (lane & 15);
            int ch  = ks * 2 + (lane >> 4);
            ldsm_x4(smA + row * 256 + ((ch ^ (row & 7)) << 4),
                    a[mi][0], a[mi][1], a[mi][2], a[mi][3]);
        }
        uint32_t bb[2][4];
#pragma unroll
        for (int nj = 0; nj < 2; nj++) {
            int row = wn * 32 + nj * 16 + (lane & 7) + ((lane >> 4) & 1) * 8;
            int ch  = ks * 2 + ((lane >> 3) & 1);
            ldsm_x4(smB + row * 256 + ((ch ^ (row & 7)) << 4),
                    bb[nj][0], bb[nj][1], bb[nj][2], bb[nj][3]);
        }
#pragma unroll
        for (int mi = 0; mi < 2; mi++)
#pragma unroll
            for (int nj = 0; nj < 2; nj++) {
                mma16816(acc[mi][2 * nj],     a[mi][0], a[mi][1], a[mi][2], a[mi][3],
                         bb[nj][0], bb[nj][1]);
                mma16816(acc[mi][2 * nj + 1], a[mi][0], a[mi][1], a[mi][2], a[mi][3],
                         bb[nj][2], bb[nj][3]);
            }
    }

#pragma unroll
    for (int mi = 0; mi < 2; mi++) {
        int px = pix0 + wm * 32 + mi * 16 + (lane >> 2);
#pragma unroll
        for (int ni = 0; ni < 4; ni++) {
            int dch = wn * 32 + ni * 8 + 2 * (lane & 3);
            float* d = acc[mi][ni];
            *(__half2*)(g_uh + (size_t)px * CH + dch)       = __floats2half2_rn(d[0], d[1]);
            *(__half2*)(g_uh + (size_t)(px + 8) * CH + dch) = __floats2half2_rn(d[2], d[3]);
        }
    }
}

// ---------------- Kernel 2: sampling + attention (online, max-free) ---------
__global__ void __launch_bounds__(256, 3) k_attn(const int*   __restrict__ psf,
                                                 const float* __restrict__ delta) {
    const int tid  = threadIdx.x;
    const int lane = tid & 31;
    const int wid  = tid >> 5;
    const int half = lane >> 4;
    const int sub  = lane & 15;

    const int pix0  = blockIdx.x << 5;
    const int bbase = (pix0 >> 14) << 14;

    float dval = 0.f;
    if (lane < 16) dval = tanhf(delta[lane]) * RADIUS;
    const float dxv = __shfl_sync(0xffffffffu, dval, (sub & 7) * 2);
    const float dyv = __shfl_sync(0xffffffffu, dval, (sub & 7) * 2 + 1);

    const uint4* xb = (const uint4*)g_xh;
    const int2*  pb = (const int2*)psf;

#pragma unroll
    for (int it = 0; it < 2; it++) {
        const int pix = pix0 + (wid << 2) + (it << 1) + half;

        uint4 up = ((const uint4*)g_uh)[(size_t)pix * 16 + sub];
        __half2 uh0 = u2h(up.x), uh1 = u2h(up.y), uh2 = u2h(up.z), uh3 = u2h(up.w);

        uint32_t meta = 0, wa = 0, wb = 0, wc = 0, wd = 0;
        if (sub < 8) {
            int2 anc = pb[(size_t)pix * KPT + sub];
            float ix = (float)anc.x + dxv;
            float iy = (float)anc.y + dyv;
            float x0f = floorf(ix), y0f = floorf(iy);
            float wx1 = ix - x0f,  wy1 = iy - y0f;
            float wx0 = 1.f - wx1, wy0 = 1.f - wy1;
            int x0 = (int)x0f, y0 = (int)y0f;
            int x1 = x0 + 1,   y1 = y0 + 1;
            float vx0 = (x0 >= 0 && x0 <= WW - 1) ? 1.f : 0.f;
            float vx1 = (x1 >= 0 && x1 <= WW - 1) ? 1.f : 0.f;
            float vy0 = (y0 >= 0 && y0 <= HH - 1) ? 1.f : 0.f;
            float vy1 = (y1 >= 0 && y1 <= HH - 1) ? 1.f : 0.f;
            int cx0 = min(max(x0, 0), WW - 1);
            int cx1 = min(max(x1, 0), WW - 1);
            int cy0 = min(max(y0, 0), HH - 1);
            int cy1 = min(max(y1, 0), HH - 1);
            meta = (uint32_t)((cy0 << 7) + cx0)
                 | ((uint32_t)(cx1 - cx0) << 14)
                 | ((uint32_t)(cy1 - cy0) << 15);
            wa = h2u(__float2half2_rn(wx0 * wy0 * vx0 * vy0));
            wb = h2u(__float2half2_rn(wx1 * wy0 * vx1 * vy0));
            wc = h2u(__float2half2_rn(wx0 * wy1 * vx0 * vy1));
            wd = h2u(__float2half2_rn(wx1 * wy1 * vx1 * vy1));
        }

        float s = 0.f;
        __half2 y0 = __float2half2_rn(0.f), y1 = y0, y2 = y0, y3 = y0;

#pragma unroll
        for (int kp = 0; kp < KPT; kp++) {
            const int src = (half << 4) + kp;
            uint32_t m   = __shfl_sync(0xffffffffu, meta, src);
            __half2 w00 = u2h(__shfl_sync(0xffffffffu, wa, src));
            __half2 w10 = u2h(__shfl_sync(0xffffffffu, wb, src));
            __half2 w01 = u2h(__shfl_sync(0xffffffffu, wc, src));
            __half2 w11 = u2h(__shfl_sync(0xffffffffu, wd, src));

            int i00 = ((bbase + (int)(m & 0x3FFFu)) << 4) + sub;
            int i10 = i00 + (int)(((m >> 14) & 1u) << 4);
            int dy  = (int)(((m >> 15) & 1u) << 11);
            int i01 = i00 + dy;
            int i11 = i10 + dy;

            uint4 c00 = xb[i00], c10 = xb[i10], c01 = xb[i01], c11 = xb[i11];
            const unsigned* p00 = &c00.x;
            const unsigned* p10 = &c10.x;
            const unsigned* p01 = &c01.x;
            const unsigned* p11 = &c11.x;

            __half2 t0, t1, t2, t3;
            t0 = __hmul2(w00, u2h(p00[0]));
            t0 = __hfma2(w10, u2h(p10[0]), t0);
            t0 = __hfma2(w01, u2h(p01[0]), t0);
            t0 = __hfma2(w11, u2h(p11[0]), t0);
            t1 = __hmul2(w00, u2h(p00[1]));
            t1 = __hfma2(w10, u2h(p10[1]), t1);
            t1 = __hfma2(w01, u2h(p01[1]), t1);
            t1 = __hfma2(w11, u2h(p11[1]), t1);
            t2 = __hmul2(w00, u2h(p00[2]));
            t2 = __hfma2(w10, u2h(p10[2]), t2);
            t2 = __hfma2(w01, u2h(p01[2]), t2);
            t2 = __hfma2(w11, u2h(p11[2]), t2);
            t3 = __hmul2(w00, u2h(p00[3]));
            t3 = __hfma2(w10, u2h(p10[3]), t3);
            t3 = __hfma2(w01, u2h(p01[3]), t3);
            t3 = __hfma2(w11, u2h(p11[3]), t3);

            __half2 dp = __hmul2(uh0, t0);
            dp = __hfma2(uh1, t1, dp);
            dp = __hfma2(uh2, t2, dp);
            dp = __hfma2(uh3, t3, dp);
            float2 f = __half22float2(dp);
            float p = f.x + f.y;
#pragma unroll
            for (int mk = 1; mk <= 8; mk <<= 1)
                p += __shfl_xor_sync(0xffffffffu, p, mk);

            float e = __expf(fminf(p, 11.f));
            s += e;
            __half2 eh = __float2half2_rn(e);
            y0 = __hfma2(eh, t0, y0);
            y1 = __hfma2(eh, t1, y1);
            y2 = __hfma2(eh, t2, y2);
            y3 = __hfma2(eh, t3, y3);
        }

        __half2 invh = __float2half2_rn(1.f / s);
        uint4 st;
        st.x = h2u(__hmul2(y0, invh));
        st.y = h2u(__hmul2(y1, invh));
        st.z = h2u(__hmul2(y2, invh));
        st.w = h2u(__hmul2(y3, invh));
        *(uint4*)(g_yh + (size_t)pix * CH + sub * 8) = st;
    }
}

// ---------------- Kernel 3: out = x + W_pv @ y~  (M=128o, N=128px) ----------
// smem: W_pv [0,32K) | y B-operand [32K,64K); after MMA the dead region is
// reused as a 64-row fp32 bounce Y (34.8KB), in two rounds.
#define YST 136   // bounce stride in floats
__global__ void __launch_bounds__(256) k_gemm_o(const float* __restrict__ x,
                                                float* __restrict__ out) {
    extern __shared__ __align__(128) char sm[];
    const int tid  = threadIdx.x;
    const int lane = tid & 31, wid = tid >> 5;
    const int wm = wid & 1, wn = wid >> 1;
    const int pix0 = blockIdx.x << 7;

    load_tile<128>(g_wpvh, sm, tid);                          // A: 32KB
    load_tile<128>(g_yh + (size_t)pix0 * CH, sm + 32768, tid); // B: 32KB
    __syncthreads();

    float acc[4][4][4];
#pragma unroll
    for (int i = 0; i < 4; i++)
#pragma unroll
        for (int j = 0; j < 4; j++)
#pragma unroll
            for (int k = 0; k < 4; k++) acc[i][j][k] = 0.f;

    const uint32_t smA = smem_u32(sm);
    const uint32_t smB = smA + 32768;

#pragma unroll
    for (int ks = 0; ks < 8; ks++) {
        uint32_t a[4][4];
#pragma unroll
        for (int mi = 0; mi < 4; mi++) {
            int row = wm * 64 + mi * 16 + (lane & 15);
            int ch  = ks * 2 + (lane >> 4);
            ldsm_x4(smA + row * 256 + ((ch ^ (row & 7)) << 4),
                    a[mi][0], a[mi][1], a[mi][2], a[mi][3]);
        }
        uint32_t bb[2][4];
#pragma unroll
        for (int nj = 0; nj < 2; nj++) {
            int row = wn * 32 + nj * 16 + (lane & 7) + ((lane >> 4) & 1) * 8;
            int ch  = ks * 2 + ((lane >> 3) & 1);
            ldsm_x4(smB + row * 256 + ((ch ^ (row & 7)) << 4),
                    bb[nj][0], bb[nj][1], bb[nj][2], bb[nj][3]);
        }
#pragma unroll
        for (int mi = 0; mi < 4; mi++)
#pragma unroll
            for (int nj = 0; nj < 2; nj++) {
                mma16816(acc[mi][2 * nj],     a[mi][0], a[mi][1], a[mi][2], a[mi][3],
                         bb[nj][0], bb[nj][1]);
                mma16816(acc[mi][2 * nj + 1], a[mi][0], a[mi][1], a[mi][2], a[mi][3],
                         bb[nj][2], bb[nj][3]);
            }
    }
    __syncthreads();   // operands dead -> safe to overlay bounce buffer

    const int b   = pix0 >> 14;
    const int hw0 = pix0 & (HWSZ - 1);
    float* Y = (float*)sm;

#pragma unroll
    for (int mh = 0; mh < 2; mh++) {
        // bounce this 64-row half's fragments
        if (wm == mh) {
#pragma unroll
            for (int mi = 0; mi < 4; mi++) {
                int o = mi * 16 + (lane >> 2);        // local row 0..63
#pragma unroll
                for (int ni = 0; ni < 4; ni++) {
                    int n = wn * 32 + ni * 8 + 2 * (lane & 3);
                    float* d = acc[mi][ni];
                    *(float2*)(Y + o * YST + n)       = make_float2(d[0], d[1]);
                    *(float2*)(Y + (o + 8) * YST + n) = make_float2(d[2], d[3]);
                }
            }
        }
        __syncthreads();

        // coalesced residual epilogue: 32 lanes x float4 = full 512B row
        const int px = (tid & 31) << 2;
#pragma unroll
        for (int j = 0; j < 8; j++) {
            int r = (tid >> 5) + 8 * j;               // local row 0..63
            float4 yv = *(const float4*)(Y + r * YST + px);
            size_t g = ((size_t)b * CH + mh * 64 + r) * HWSZ + hw0 + px;
            float4 xv = *(const float4*)(x + g);
            *(float4*)(out + g) = make_float4(xv.x + yv.x, xv.y + yv.y,
                                              xv.z + yv.z, xv.w + yv.w);
        }
        __syncthreads();
    }
}

// ---------------- launcher ----------------
extern "C" void kernel_launch(void* const* d_in, const int* in_sizes, int n_in,
                              void* d_out, int out_size) {
    const float* x     = (const float*)d_in[0];
    const int*   psf   = (const int*)  d_in[1];
    const float* delta = (const float*)d_in[2];
    const float* wqkv  = (const float*)d_in[3];
    const float* wproj = (const float*)d_in[4];
    float* out = (float*)d_out;

    const int smem_u = 49152 + 128 * SST * 2;   // 67584
    const int smem_o = 65536;
    cudaFuncSetAttribute(k_prep_u, cudaFuncAttributeMaxDynamicSharedMemorySize, smem_u);
    cudaFuncSetAttribute(k_gemm_o, cudaFuncAttributeMaxDynamicSharedMemorySize, smem_o);

    k_wall<<<32, 256>>>(wqkv, wproj);
    k_prep_u<<<NPIX / 64, 256, smem_u>>>(x);
    k_attn<<<NPIX / 32, 256>>>(psf, delta);
    k_gemm_o<<<NPIX / 128, 256, smem_o>>>(x, out);
}

// round 15
// speedup vs baseline: 1.2170x; 1.2170x over previous
#include <cuda_runtime.h>
#include <cuda_fp16.h>
#include <cstdint>

#define BATCH 4
#define CH    128
#define HH    128
#define WW    128
#define KPT   8
#define HWSZ  (HH * WW)           // 16384
#define NPIX  (BATCH * HWSZ)      // 65536
#define RADIUS 4.0f
#define SCALE 0.08838834764831845f  // C^-0.5

// Scratch buffers (pixel-major / NHWC, fp16)
__device__ __half g_xh [NPIX * CH];   // x fp16 NHWC (gather + GEMM operand)
__device__ __half g_uh [NPIX * CH];   // u = (SCALE*GT) @ x
__device__ __half g_yh [NPIX * CH];   // y~ = sum_k attn * x~
__device__ __half g_gth [CH * CH];    // GT[d][c] * SCALE, K-contig
__device__ __half g_wpvh[CH * CH];    // W_pv[o][c], K-contig

// ---------------- helpers ----------------
__device__ __forceinline__ uint32_t smem_u32(const void* p) {
    uint32_t a;
    asm("{ .reg .u64 t; cvta.to.shared.u64 t, %1; cvt.u32.u64 %0, t; }"
        : "=r"(a) : "l"(p));
    return a;
}
__device__ __forceinline__ unsigned h2u(__half2 h) { return *reinterpret_cast<unsigned*>(&h); }
__device__ __forceinline__ __half2 u2h(unsigned u) { return *reinterpret_cast<__half2*>(&u); }

__device__ __forceinline__ void ldsm_x4(uint32_t a, uint32_t& r0, uint32_t& r1,
                                        uint32_t& r2, uint32_t& r3) {
    asm volatile("ldmatrix.sync.aligned.m8n8.x4.shared.b16 {%0,%1,%2,%3}, [%4];"
                 : "=r"(r0), "=r"(r1), "=r"(r2), "=r"(r3) : "r"(a));
}
__device__ __forceinline__ void ldsm_x4_t(uint32_t a, uint32_t& r0, uint32_t& r1,
                                          uint32_t& r2, uint32_t& r3) {
    asm volatile("ldmatrix.sync.aligned.m8n8.x4.trans.shared.b16 {%0,%1,%2,%3}, [%4];"
                 : "=r"(r0), "=r"(r1), "=r"(r2), "=r"(r3) : "r"(a));
}
__device__ __forceinline__ void mma16816(float* d, uint32_t a0, uint32_t a1,
                                         uint32_t a2, uint32_t a3,
                                         uint32_t b0, uint32_t b1) {
    asm volatile("mma.sync.aligned.m16n8k16.row.col.f32.f16.f16.f32 "
                 "{%0,%1,%2,%3},{%4,%5,%6,%7},{%8,%9},{%0,%1,%2,%3};"
                 : "+f"(d[0]), "+f"(d[1]), "+f"(d[2]), "+f"(d[3])
                 : "r"(a0), "r"(a1), "r"(a2), "r"(a3), "r"(b0), "r"(b1));
}

#define CP_COMMIT() asm volatile("cp.async.commit_group;" ::: "memory")
#define CP_WAIT0()  asm volatile("cp.async.wait_group 0;" ::: "memory")

// async copy of an Rx128 fp16 K-contig tile into XOR-swizzled smem
template <int ROWS>
__device__ __forceinline__ void load_tile_async(const __half* __restrict__ src,
                                                uint32_t dst, int tid) {
#pragma unroll
    for (int i = 0; i < ROWS / 16; i++) {
        int idx = i * 256 + tid;           // chunks of 16B
        int r   = idx >> 4;
        int c   = idx & 15;
        uint32_t s = dst + r * 256 + ((c ^ (r & 7)) << 4);
        const void* g = src + (size_t)r * 128 + c * 8;
        asm volatile("cp.async.cg.shared.global [%0], [%1], 16;"
                     :: "r"(s), "l"(g) : "memory");
    }
}

// ---------------- Kernel 0: weight fold (fp16, SCALE folded into GT) --------
__global__ void __launch_bounds__(256) k_wall(const float* __restrict__ wqkv,
                                              const float* __restrict__ wproj) {
    __shared__ float sv[CH];
    __shared__ float red[256];
    const int blk = blockIdx.x;
    const int tid = threadIdx.x;
    const int c   = tid & 127;
    const int hf  = tid >> 7;

    if (blk < 128) {
        const int d = blk;
        if (tid < CH) sv[tid] = wqkv[(128 + tid) * CH + d];   // Wk[o][d]
        __syncthreads();
        float acc = 0.f;
#pragma unroll 16
        for (int o = 0; o < 64; o++) {
            int oo = hf * 64 + o;
            acc += wqkv[oo * CH + c] * sv[oo];                // Wq[o][c]
        }
        red[tid] = acc;
        __syncthreads();
        if (tid < CH)
            g_gth[d * CH + c] = __float2half((red[tid] + red[tid + 128]) * SCALE);
    } else {
        const int o = blk - 128;
        if (tid < CH) sv[tid] = wproj[o * CH + tid];
        __syncthreads();
        float acc = 0.f;
#pragma unroll 16
        for (int m = 0; m < 64; m++) {
            int mm = hf * 64 + m;
            acc += sv[mm] * wqkv[(256 + mm) * CH + c];        // Wv[m][c]
        }
        red[tid] = acc;
        __syncthreads();
        if (tid < CH) g_wpvh[o * CH + c] = __float2half(red[tid] + red[tid + 128]);
    }
}

// ---------------- Kernel 1 (fused): x NCHW -> A operand (=xh) -> u GEMM -----
// smem: A operand [0,16K) | GT [16K,48K) | staging S [48K, 48K+18432)
// GT is fetched with cp.async at kernel start and waited on only after the
// transpose phases -> its latency hides behind ~6us of phase-1 work.
#define SST 72   // staging stride in halfs (144B: conflict-free ldmatrix rows)
__global__ void __launch_bounds__(256) k_prep_u(const float* __restrict__ x) {
    extern __shared__ __align__(128) char sm[];
    const int tid  = threadIdx.x;
    const int lane = tid & 31, wid = tid >> 5;
    const int wm = wid & 1, wn = wid >> 1;
    const int pix0 = blockIdx.x << 6;
    const int b    = pix0 >> 14;
    const int hw0  = pix0 & (HWSZ - 1);

    const uint32_t smA = smem_u32(sm);
    const uint32_t smB = smA + 16384;

    load_tile_async<128>(g_gth, smB, tid);                 // GT (32KB) async
    CP_COMMIT();

    __half* S = (__half*)(sm + 49152);

    // Phase 1: coalesced stage
#pragma unroll
    for (int i = 0; i < 8; i++) {
        int idx = i * 256 + tid;
        int c = idx >> 4, j4 = idx & 15;
        float4 v = *(const float4*)(x + ((size_t)b * CH + c) * HWSZ + hw0 + j4 * 4);
        *(__half2*)(S + c * SST + j4 * 4)     = __floats2half2_rn(v.x, v.y);
        *(__half2*)(S + c * SST + j4 * 4 + 2) = __floats2half2_rn(v.z, v.w);
    }
    __syncthreads();

    // Phase 1c: hardware transpose into swizzled A operand
#pragma unroll
    for (int i = 0; i < 4; i++) {
        int g  = wid + 8 * i;              // tile group 0..31
        int c0 = (g >> 3) << 5;            // 32-channel span
        int pb = g & 7;                    // px block (8 px)
        uint32_t src = smem_u32(S + (c0 + ((lane >> 3) << 3) + (lane & 7)) * SST + pb * 8);
        uint32_t r0, r1, r2, r3;
        ldsm_x4_t(src, r0, r1, r2, r3);
        int px = (pb << 3) + (lane >> 2);
        uint32_t rr[4] = {r0, r1, r2, r3};
#pragma unroll
        for (int k = 0; k < 4; k++) {
            int c2    = (c0 >> 1) + (k << 2) + (lane & 3);
            int chunk = c2 >> 2;
            int inner = (c2 & 3) << 2;
            *(uint32_t*)(sm + px * 256 + ((chunk ^ (px & 7)) << 4) + inner) = rr[k];
        }
    }
    __syncthreads();

    // Phase 1b: write g_xh NHWC from the swizzled operand
#pragma unroll
    for (int i = 0; i < 4; i++) {
        int idx = i * 256 + tid;
        int px = idx >> 4, q = idx & 15;
        uint4 v = *(const uint4*)(sm + px * 256 + ((q ^ (px & 7)) << 4));
        *(uint4*)(g_xh + (size_t)(pix0 + px) * CH + q * 8) = v;
    }

    // wait for GT before the MMA reads it
    CP_WAIT0();
    __syncthreads();

    // Phase 2: u = A @ GT^T  (M=64px, N=128dch)
    float acc[2][4][4];
#pragma unroll
    for (int i = 0; i < 2; i++)
#pragma unroll
        for (int j = 0; j < 4; j++)
#pragma unroll
            for (int k = 0; k < 4; k++) acc[i][j][k] = 0.f;

#pragma unroll
    for (int ks = 0; ks < 8; ks++) {
        uint32_t a[2][4];
#pragma unroll
        for (int mi = 0; mi < 2; mi++) {
            int row = wm * 32 + mi * 16 + (lane & 15);
            int ch  = ks * 2 + (lane >> 4);
            ldsm_x4(smA + row * 256 + ((ch ^ (row & 7)) << 4),
                    a[mi][0], a[mi][1], a[mi][2], a[mi][3]);
        }
        uint32_t bb[2][4];
#pragma unroll
        for (int nj = 0; nj < 2; nj++) {
            int row = wn * 32 + nj * 16 + (lane & 7) + ((lane >> 4) & 1) * 8;
            int ch  = ks * 2 + ((lane >> 3) & 1);
            ldsm_x4(smB + row * 256 + ((ch ^ (row & 7)) << 4),
                    bb[nj][0], bb[nj][1], bb[nj][2], bb[nj][3]);
        }
#pragma unroll
        for (int mi = 0; mi < 2; mi++)
#pragma unroll
            for (int nj = 0; nj < 2; nj++) {
                mma16816(acc[mi][2 * nj],     a[mi][0], a[mi][1], a[mi][2], a[mi][3],
                         bb[nj][0], bb[nj][1]);
                mma16816(acc[mi][2 * nj + 1], a[mi][0], a[mi][1], a[mi][2], a[mi][3],
                         bb[nj][2], bb[nj][3]);
            }
    }

#pragma unroll
    for (int mi = 0; mi < 2; mi++) {
        int px = pix0 + wm * 32 + mi * 16 + (lane >> 2);
#pragma unroll
        for (int ni = 0; ni < 4; ni++) {
            int dch = wn * 32 + ni * 8 + 2 * (lane & 3);
            float* d = acc[mi][ni];
            *(__half2*)(g_uh + (size_t)px * CH + dch)       = __floats2half2_rn(d[0], d[1]);
            *(__half2*)(g_uh + (size_t)(px + 8) * CH + dch) = __floats2half2_rn(d[2], d[3]);
        }
    }
}

// ---------------- Kernel 2: sampling + attention (online, max-free) ---------
__global__ void __launch_bounds__(256, 3) k_attn(const int*   __restrict__ psf,
                                                 const float* __restrict__ delta) {
    const int tid  = threadIdx.x;
    const int lane = tid & 31;
    const int wid  = tid >> 5;
    const int half = lane >> 4;
    const int sub  = lane & 15;

    const int pix0  = blockIdx.x << 5;
    const int bbase = (pix0 >> 14) << 14;

    float dval = 0.f;
    if (lane < 16) dval = tanhf(delta[lane]) * RADIUS;
    const float dxv = __shfl_sync(0xffffffffu, dval, (sub & 7) * 2);
    const float dyv = __shfl_sync(0xffffffffu, dval, (sub & 7) * 2 + 1);

    const uint4* xb = (const uint4*)g_xh;
    const int2*  pb = (const int2*)psf;

#pragma unroll
    for (int it = 0; it < 2; it++) {
        const int pix = pix0 + (wid << 2) + (it << 1) + half;

        uint4 up = ((const uint4*)g_uh)[(size_t)pix * 16 + sub];
        __half2 uh0 = u2h(up.x), uh1 = u2h(up.y), uh2 = u2h(up.z), uh3 = u2h(up.w);

        uint32_t meta = 0, wa = 0, wb = 0, wc = 0, wd = 0;
        if (sub < 8) {
            int2 anc = pb[(size_t)pix * KPT + sub];
            float ix = (float)anc.x + dxv;
            float iy = (float)anc.y + dyv;
            float x0f = floorf(ix), y0f = floorf(iy);
            float wx1 = ix - x0f,  wy1 = iy - y0f;
            float wx0 = 1.f - wx1, wy0 = 1.f - wy1;
            int x0 = (int)x0f, y0 = (int)y0f;
            int x1 = x0 + 1,   y1 = y0 + 1;
            float vx0 = (x0 >= 0 && x0 <= WW - 1) ? 1.f : 0.f;
            float vx1 = (x1 >= 0 && x1 <= WW - 1) ? 1.f : 0.f;
            float vy0 = (y0 >= 0 && y0 <= HH - 1) ? 1.f : 0.f;
            float vy1 = (y1 >= 0 && y1 <= HH - 1) ? 1.f : 0.f;
            int cx0 = min(max(x0, 0), WW - 1);
            int cx1 = min(max(x1, 0), WW - 1);
            int cy0 = min(max(y0, 0), HH - 1);
            int cy1 = min(max(y1, 0), HH - 1);
            meta = (uint32_t)((cy0 << 7) + cx0)
                 | ((uint32_t)(cx1 - cx0) << 14)
                 | ((uint32_t)(cy1 - cy0) << 15);
            wa = h2u(__float2half2_rn(wx0 * wy0 * vx0 * vy0));
            wb = h2u(__float2half2_rn(wx1 * wy0 * vx1 * vy0));
            wc = h2u(__float2half2_rn(wx0 * wy1 * vx0 * vy1));
            wd = h2u(__float2half2_rn(wx1 * wy1 * vx1 * vy1));
        }

        float s = 0.f;
        __half2 y0 = __float2half2_rn(0.f), y1 = y0, y2 = y0, y3 = y0;

#pragma unroll
        for (int kp = 0; kp < KPT; kp++) {
            const int src = (half << 4) + kp;
            uint32_t m   = __shfl_sync(0xffffffffu, meta, src);
            __half2 w00 = u2h(__shfl_sync(0xffffffffu, wa, src));
            __half2 w10 = u2h(__shfl_sync(0xffffffffu, wb, src));
            __half2 w01 = u2h(__shfl_sync(0xffffffffu, wc, src));
            __half2 w11 = u2h(__shfl_sync(0xffffffffu, wd, src));

            int i00 = ((bbase + (int)(m & 0x3FFFu)) << 4) + sub;
            int i10 = i00 + (int)(((m >> 14) & 1u) << 4);
            int dy  = (int)(((m >> 15) & 1u) << 11);
            int i01 = i00 + dy;
            int i11 = i10 + dy;

            uint4 c00 = xb[i00], c10 = xb[i10], c01 = xb[i01], c11 = xb[i11];
            const unsigned* p00 = &c00.x;
            const unsigned* p10 = &c10.x;
            const unsigned* p01 = &c01.x;
            const unsigned* p11 = &c11.x;

            __half2 t0, t1, t2, t3;
            t0 = __hmul2(w00, u2h(p00[0]));
            t0 = __hfma2(w10, u2h(p10[0]), t0);
            t0 = __hfma2(w01, u2h(p01[0]), t0);
            t0 = __hfma2(w11, u2h(p11[0]), t0);
            t1 = __hmul2(w00, u2h(p00[1]));
            t1 = __hfma2(w10, u2h(p10[1]), t1);
            t1 = __hfma2(w01, u2h(p01[1]), t1);
            t1 = __hfma2(w11, u2h(p11[1]), t1);
            t2 = __hmul2(w00, u2h(p00[2]));
            t2 = __hfma2(w10, u2h(p10[2]), t2);
            t2 = __hfma2(w01, u2h(p01[2]), t2);
            t2 = __hfma2(w11, u2h(p11[2]), t2);
            t3 = __hmul2(w00, u2h(p00[3]));
            t3 = __hfma2(w10, u2h(p10[3]), t3);
            t3 = __hfma2(w01, u2h(p01[3]), t3);
            t3 = __hfma2(w11, u2h(p11[3]), t3);

            __half2 dp = __hmul2(uh0, t0);
            dp = __hfma2(uh1, t1, dp);
            dp = __hfma2(uh2, t2, dp);
            dp = __hfma2(uh3, t3, dp);
            float2 f = __half22float2(dp);
            float p = f.x + f.y;
#pragma unroll
            for (int mk = 1; mk <= 8; mk <<= 1)
                p += __shfl_xor_sync(0xffffffffu, p, mk);

            float e = __expf(fminf(p, 11.f));
            s += e;
            __half2 eh = __float2half2_rn(e);
            y0 = __hfma2(eh, t0, y0);
            y1 = __hfma2(eh, t1, y1);
            y2 = __hfma2(eh, t2, y2);
            y3 = __hfma2(eh, t3, y3);
        }

        __half2 invh = __float2half2_rn(1.f / s);
        uint4 st;
        st.x = h2u(__hmul2(y0, invh));
        st.y = h2u(__hmul2(y1, invh));
        st.z = h2u(__hmul2(y2, invh));
        st.w = h2u(__hmul2(y3, invh));
        *(uint4*)(g_yh + (size_t)pix * CH + sub * 8) = st;
    }
}

// ---------------- Kernel 3: out = x + W_pv @ y~  (bounced, overlaid) --------
// smem: W_pv [0,32K) | y B-operand [32K,48K); after MMA the SAME region is
// reused as the fp32 bounce buffer Y (36.9KB) -> total 48KB, 4 CTAs/SM.
#define YST 72   // bounce stride in floats
__global__ void __launch_bounds__(256) k_gemm_o(const float* __restrict__ x,
                                                float* __restrict__ out) {
    extern __shared__ __align__(128) char sm[];
    const int tid  = threadIdx.x;
    const int lane = tid & 31, wid = tid >> 5;
    const int wm = wid & 1, wn = wid >> 1;
    const int pix0 = blockIdx.x << 6;

    const uint32_t smA = smem_u32(sm);
    const uint32_t smB = smA + 32768;

    load_tile_async<128>(g_wpvh, smA, tid);                // A: weights (32KB)
    load_tile_async<64>(g_yh + (size_t)pix0 * CH, smB, tid); // B: y (16KB)
    CP_COMMIT();
    CP_WAIT0();
    __syncthreads();

    float acc[4][2][4];
#pragma unroll
    for (int i = 0; i < 4; i++)
#pragma unroll
        for (int j = 0; j < 2; j++)
#pragma unroll
            for (int k = 0; k < 4; k++) acc[i][j][k] = 0.f;

#pragma unroll
    for (int ks = 0; ks < 8; ks++) {
        uint32_t a[4][4];
#pragma unroll
        for (int mi = 0; mi < 4; mi++) {
            int row = wm * 64 + mi * 16 + (lane & 15);
            int ch  = ks * 2 + (lane >> 4);
            ldsm_x4(smA + row * 256 + ((ch ^ (row & 7)) << 4),
                    a[mi][0], a[mi][1], a[mi][2], a[mi][3]);
        }
        uint32_t bb[4];
        {
            int row = wn * 16 + (lane & 7) + ((lane >> 4) & 1) * 8;
            int ch  = ks * 2 + ((lane >> 3) & 1);
            ldsm_x4(smB + row * 256 + ((ch ^ (row & 7)) << 4),
                    bb[0], bb[1], bb[2], bb[3]);
        }
#pragma unroll
        for (int mi = 0; mi < 4; mi++) {
            mma16816(acc[mi][0], a[mi][0], a[mi][1], a[mi][2], a[mi][3], bb[0], bb[1]);
            mma16816(acc[mi][1], a[mi][0], a[mi][1], a[mi][2], a[mi][3], bb[2], bb[3]);
        }
    }
    __syncthreads();   // operands dead -> safe to overlay bounce buffer

    // bounce fragments -> fp32 smem (overlaid on operand region)
    float* Y = (float*)sm;
#pragma unroll
    for (int mi = 0; mi < 4; mi++) {
        int o = wm * 64 + mi * 16 + (lane >> 2);
#pragma unroll
        for (int ni = 0; ni < 2; ni++) {
            int n = wn * 16 + ni * 8 + 2 * (lane & 3);
            float* d = acc[mi][ni];
            *(float2*)(Y + o * YST + n)       = make_float2(d[0], d[1]);
            *(float2*)(Y + (o + 8) * YST + n) = make_float2(d[2], d[3]);
        }
    }
    __syncthreads();

    // coalesced residual epilogue: lanes 0-15 span a full 256B row
    const int b   = pix0 >> 14;
    const int hw0 = pix0 & (HWSZ - 1);
    const int px  = (tid & 15) << 2;
#pragma unroll
    for (int j = 0; j < 8; j++) {
        int r = (tid >> 4) + 16 * j;
        float4 yv = *(const float4*)(Y + r * YST + px);
        size_t g = ((size_t)b * CH + r) * HWSZ + hw0 + px;
        float4 xv = *(const float4*)(x + g);
        *(float4*)(out + g) = make_float4(xv.x + yv.x, xv.y + yv.y,
                                          xv.z + yv.z, xv.w + yv.w);
    }
}

// ---------------- launcher ----------------
extern "C" void kernel_launch(void* const* d_in, const int* in_sizes, int n_in,
                              void* d_out, int out_size) {
    const float* x     = (const float*)d_in[0];
    const int*   psf   = (const int*)  d_in[1];
    const float* delta = (const float*)d_in[2];
    const float* wqkv  = (const float*)d_in[3];
    const float* wproj = (const float*)d_in[4];
    float* out = (float*)d_out;

    const int smem_u = 49152 + 128 * SST * 2;   // 67584
    const int smem_o = 49152;                   // operands; bounce overlaid
    cudaFuncSetAttribute(k_prep_u, cudaFuncAttributeMaxDynamicSharedMemorySize, smem_u);
    cudaFuncSetAttribute(k_gemm_o, cudaFuncAttributeMaxDynamicSharedMemorySize, smem_o);

    k_wall<<<256, 256>>>(wqkv, wproj);
    k_prep_u<<<NPIX / 64, 256, smem_u>>>(x);
    k_attn<<<NPIX / 32, 256>>>(psf, delta);
    k_gemm_o<<<NPIX / 64, 256, smem_o>>>(x, out);
}

// round 16
// speedup vs baseline: 1.2233x; 1.0052x over previous
#include <cuda_runtime.h>
#include <cuda_fp16.h>
#include <cstdint>

#define BATCH 4
#define CH    128
#define HH    128
#define WW    128
#define KPT   8
#define HWSZ  (HH * WW)           // 16384
#define NPIX  (BATCH * HWSZ)      // 65536
#define RADIUS 4.0f
#define SCALE 0.08838834764831845f  // C^-0.5

// Scratch buffers (pixel-major / NHWC, fp16)
__device__ __half g_xh [NPIX * CH];   // x fp16 NHWC (gather + GEMM operand)
__device__ __half g_uh [NPIX * CH];   // u = (SCALE*GT) @ x
__device__ __half g_yh [NPIX * CH];   // y~ = sum_k attn * x~
__device__ __half g_gth [CH * CH];    // GT[d][c] * SCALE, K-contig
__device__ __half g_wpvh[CH * CH];    // W_pv[o][c], K-contig

// ---------------- helpers ----------------
__device__ __forceinline__ uint32_t smem_u32(const void* p) {
    uint32_t a;
    asm("{ .reg .u64 t; cvta.to.shared.u64 t, %1; cvt.u32.u64 %0, t; }"
        : "=r"(a) : "l"(p));
    return a;
}
__device__ __forceinline__ unsigned h2u(__half2 h) { return *reinterpret_cast<unsigned*>(&h); }
__device__ __forceinline__ __half2 u2h(unsigned u) { return *reinterpret_cast<__half2*>(&u); }

__device__ __forceinline__ void ldsm_x4(uint32_t a, uint32_t& r0, uint32_t& r1,
                                        uint32_t& r2, uint32_t& r3) {
    asm volatile("ldmatrix.sync.aligned.m8n8.x4.shared.b16 {%0,%1,%2,%3}, [%4];"
                 : "=r"(r0), "=r"(r1), "=r"(r2), "=r"(r3) : "r"(a));
}
__device__ __forceinline__ void ldsm_x4_t(uint32_t a, uint32_t& r0, uint32_t& r1,
                                          uint32_t& r2, uint32_t& r3) {
    asm volatile("ldmatrix.sync.aligned.m8n8.x4.trans.shared.b16 {%0,%1,%2,%3}, [%4];"
                 : "=r"(r0), "=r"(r1), "=r"(r2), "=r"(r3) : "r"(a));
}
__device__ __forceinline__ void mma16816(float* d, uint32_t a0, uint32_t a1,
                                         uint32_t a2, uint32_t a3,
                                         uint32_t b0, uint32_t b1) {
    asm volatile("mma.sync.aligned.m16n8k16.row.col.f32.f16.f16.f32 "
                 "{%0,%1,%2,%3},{%4,%5,%6,%7},{%8,%9},{%0,%1,%2,%3};"
                 : "+f"(d[0]), "+f"(d[1]), "+f"(d[2]), "+f"(d[3])
                 : "r"(a0), "r"(a1), "r"(a2), "r"(a3), "r"(b0), "r"(b1));
}

#define CP_COMMIT() asm volatile("cp.async.commit_group;" ::: "memory")
#define CP_WAIT0()  asm volatile("cp.async.wait_group 0;" ::: "memory")

// async copy of an Rx128 fp16 K-contig tile into XOR-swizzled smem
template <int ROWS>
__device__ __forceinline__ void load_tile_async(const __half* __restrict__ src,
                                                uint32_t dst, int tid) {
#pragma unroll
    for (int i = 0; i < ROWS / 16; i++) {
        int idx = i * 256 + tid;           // chunks of 16B
        int r   = idx >> 4;
        int c   = idx & 15;
        uint32_t s = dst + r * 256 + ((c ^ (r & 7)) << 4);
        const void* g = src + (size_t)r * 128 + c * 8;
        asm volatile("cp.async.cg.shared.global [%0], [%1], 16;"
                     :: "r"(s), "l"(g) : "memory");
    }
}

// ---------------- Kernel I: fused (x NCHW -> xh NHWC) + weight fold --------
// blocks 0..1023: 64-px transpose tile (ldmatrix-trans path, 34.8KB smem)
// blocks 1024..1279: weight fold (GT / W_pv rows)
#define SST 72   // staging stride in halfs (144B: conflict-free ldmatrix rows)
__global__ void __launch_bounds__(256) k_init(const float* __restrict__ x,
                                              const float* __restrict__ wqkv,
                                              const float* __restrict__ wproj) {
    extern __shared__ __align__(128) char sm[];
    const int blk = blockIdx.x;
    const int tid = threadIdx.x;

    if (blk < 1024) {
        const int lane = tid & 31, wid = tid >> 5;
        const int pix0 = blk << 6;
        const int b    = pix0 >> 14;
        const int hw0  = pix0 & (HWSZ - 1);

        __half* S = (__half*)(sm + 16384);    // staging [48K..] -> here 16K..

        // Phase 1: coalesced stage x -> fp16 S[c][px]
#pragma unroll
        for (int i = 0; i < 8; i++) {
            int idx = i * 256 + tid;
            int c = idx >> 4, j4 = idx & 15;
            float4 v = *(const float4*)(x + ((size_t)b * CH + c) * HWSZ + hw0 + j4 * 4);
            *(__half2*)(S + c * SST + j4 * 4)     = __floats2half2_rn(v.x, v.y);
            *(__half2*)(S + c * SST + j4 * 4 + 2) = __floats2half2_rn(v.z, v.w);
        }
        __syncthreads();

        // Phase 1c: hardware transpose into swizzled NHWC tile at sm[0,16K)
#pragma unroll
        for (int i = 0; i < 4; i++) {
            int g  = wid + 8 * i;              // tile group 0..31
            int c0 = (g >> 3) << 5;            // 32-channel span
            int pb = g & 7;                    // px block (8 px)
            uint32_t src = smem_u32(S + (c0 + ((lane >> 3) << 3) + (lane & 7)) * SST + pb * 8);
            uint32_t r0, r1, r2, r3;
            ldsm_x4_t(src, r0, r1, r2, r3);
            int px = (pb << 3) + (lane >> 2);
            uint32_t rr[4] = {r0, r1, r2, r3};
#pragma unroll
            for (int k = 0; k < 4; k++) {
                int c2    = (c0 >> 1) + (k << 2) + (lane & 3);
                int chunk = c2 >> 2;
                int inner = (c2 & 3) << 2;
                *(uint32_t*)(sm + px * 256 + ((chunk ^ (px & 7)) << 4) + inner) = rr[k];
            }
        }
        __syncthreads();

        // Phase 1b: coalesced write of g_xh NHWC
#pragma unroll
        for (int i = 0; i < 4; i++) {
            int idx = i * 256 + tid;
            int px = idx >> 4, q = idx & 15;
            uint4 v = *(const uint4*)(sm + px * 256 + ((q ^ (px & 7)) << 4));
            *(uint4*)(g_xh + (size_t)(pix0 + px) * CH + q * 8) = v;
        }
    } else {
        // ---- weight fold ----
        float* sv  = (float*)sm;              // [128]
        float* red = sv + 128;                // [256]
        const int w  = blk - 1024;            // 0..255
        const int c  = tid & 127;
        const int hf = tid >> 7;

        if (w < 128) {
            const int d = w;
            if (tid < CH) sv[tid] = wqkv[(128 + tid) * CH + d];   // Wk[o][d]
            __syncthreads();
            float acc = 0.f;
#pragma unroll 16
            for (int o = 0; o < 64; o++) {
                int oo = hf * 64 + o;
                acc += wqkv[oo * CH + c] * sv[oo];                // Wq[o][c]
            }
            red[tid] = acc;
            __syncthreads();
            if (tid < CH)
                g_gth[d * CH + c] = __float2half((red[tid] + red[tid + 128]) * SCALE);
        } else {
            const int o = w - 128;
            if (tid < CH) sv[tid] = wproj[o * CH + tid];
            __syncthreads();
            float acc = 0.f;
#pragma unroll 16
            for (int m = 0; m < 64; m++) {
                int mm = hf * 64 + m;
                acc += sv[mm] * wqkv[(256 + mm) * CH + c];        // Wv[m][c]
            }
            red[tid] = acc;
            __syncthreads();
            if (tid < CH) g_wpvh[o * CH + c] = __float2half(red[tid] + red[tid + 128]);
        }
    }
}

// ---------------- Kernel 1: u = xh @ (SCALE*GT)^T  (M=64px, N=128dch) ------
// Both operands via cp.async; xh tile is L2-hot (just produced by k_init).
__global__ void __launch_bounds__(256) k_gemm_u() {
    extern __shared__ __align__(128) char sm[];
    const int tid  = threadIdx.x;
    const int lane = tid & 31, wid = tid >> 5;
    const int wm = wid & 1, wn = wid >> 1;
    const int pix0 = blockIdx.x << 6;

    const uint32_t smA = smem_u32(sm);
    const uint32_t smB = smA + 16384;

    load_tile_async<64>(g_xh + (size_t)pix0 * CH, smA, tid);   // A: 16KB
    load_tile_async<128>(g_gth, smB, tid);                     // B: 32KB
    CP_COMMIT();
    CP_WAIT0();
    __syncthreads();

    float acc[2][4][4];
#pragma unroll
    for (int i = 0; i < 2; i++)
#pragma unroll
        for (int j = 0; j < 4; j++)
#pragma unroll
            for (int k = 0; k < 4; k++) acc[i][j][k] = 0.f;

#pragma unroll
    for (int ks = 0; ks < 8; ks++) {
        uint32_t a[2][4];
#pragma unroll
        for (int mi = 0; mi < 2; mi++) {
            int row = wm * 32 + mi * 16 + (lane & 15);
            int ch  = ks * 2 + (lane >> 4);
            ldsm_x4(smA + row * 256 + ((ch ^ (row & 7)) << 4),
                    a[mi][0], a[mi][1], a[mi][2], a[mi][3]);
        }
        uint32_t bb[2][4];
#pragma unroll
        for (int nj = 0; nj < 2; nj++) {
            int row = wn * 32 + nj * 16 + (lane & 7) + ((lane >> 4) & 1) * 8;
            int ch  = ks * 2 + ((lane >> 3) & 1);
            ldsm_x4(smB + row * 256 + ((ch ^ (row & 7)) << 4),
                    bb[nj][0], bb[nj][1], bb[nj][2], bb[nj][3]);
        }
#pragma unroll
        for (int mi = 0; mi < 2; mi++)
#pragma unroll
            for (int nj = 0; nj < 2; nj++) {
                mma16816(acc[mi][2 * nj],     a[mi][0], a[mi][1], a[mi][2], a[mi][3],
                         bb[nj][0], bb[nj][1]);
                mma16816(acc[mi][2 * nj + 1], a[mi][0], a[mi][1], a[mi][2], a[mi][3],
                         bb[nj][2], bb[nj][3]);
            }
    }

#pragma unroll
    for (int mi = 0; mi < 2; mi++) {
        int px = pix0 + wm * 32 + mi * 16 + (lane >> 2);
#pragma unroll
        for (int ni = 0; ni < 4; ni++) {
            int dch = wn * 32 + ni * 8 + 2 * (lane & 3);
            float* d = acc[mi][ni];
            *(__half2*)(g_uh + (size_t)px * CH + dch)       = __floats2half2_rn(d[0], d[1]);
            *(__half2*)(g_uh + (size_t)(px + 8) * CH + dch) = __floats2half2_rn(d[2], d[3]);
        }
    }
}

// ---------------- Kernel 2: sampling + attention (online, max-free) ---------
__global__ void __launch_bounds__(256, 3) k_attn(const int*   __restrict__ psf,
                                                 const float* __restrict__ delta) {
    const int tid  = threadIdx.x;
    const int lane = tid & 31;
    const int wid  = tid >> 5;
    const int half = lane >> 4;
    const int sub  = lane & 15;

    const int pix0  = blockIdx.x << 5;
    const int bbase = (pix0 >> 14) << 14;

    float dval = 0.f;
    if (lane < 16) dval = tanhf(delta[lane]) * RADIUS;
    const float dxv = __shfl_sync(0xffffffffu, dval, (sub & 7) * 2);
    const float dyv = __shfl_sync(0xffffffffu, dval, (sub & 7) * 2 + 1);

    const uint4* xb = (const uint4*)g_xh;
    const int2*  pb = (const int2*)psf;

#pragma unroll
    for (int it = 0; it < 2; it++) {
        const int pix = pix0 + (wid << 2) + (it << 1) + half;

        uint4 up = ((const uint4*)g_uh)[(size_t)pix * 16 + sub];
        __half2 uh0 = u2h(up.x), uh1 = u2h(up.y), uh2 = u2h(up.z), uh3 = u2h(up.w);

        uint32_t meta = 0, wa = 0, wb = 0, wc = 0, wd = 0;
        if (sub < 8) {
            int2 anc = pb[(size_t)pix * KPT + sub];
            float ix = (float)anc.x + dxv;
            float iy = (float)anc.y + dyv;
            float x0f = floorf(ix), y0f = floorf(iy);
            float wx1 = ix - x0f,  wy1 = iy - y0f;
            float wx0 = 1.f - wx1, wy0 = 1.f - wy1;
            int x0 = (int)x0f, y0 = (int)y0f;
            int x1 = x0 + 1,   y1 = y0 + 1;
            float vx0 = (x0 >= 0 && x0 <= WW - 1) ? 1.f : 0.f;
            float vx1 = (x1 >= 0 && x1 <= WW - 1) ? 1.f : 0.f;
            float vy0 = (y0 >= 0 && y0 <= HH - 1) ? 1.f : 0.f;
            float vy1 = (y1 >= 0 && y1 <= HH - 1) ? 1.f : 0.f;
            int cx0 = min(max(x0, 0), WW - 1);
            int cx1 = min(max(x1, 0), WW - 1);
            int cy0 = min(max(y0, 0), HH - 1);
            int cy1 = min(max(y1, 0), HH - 1);
            meta = (uint32_t)((cy0 << 7) + cx0)
                 | ((uint32_t)(cx1 - cx0) << 14)
                 | ((uint32_t)(cy1 - cy0) << 15);
            wa = h2u(__float2half2_rn(wx0 * wy0 * vx0 * vy0));
            wb = h2u(__float2half2_rn(wx1 * wy0 * vx1 * vy0));
            wc = h2u(__float2half2_rn(wx0 * wy1 * vx0 * vy1));
            wd = h2u(__float2half2_rn(wx1 * wy1 * vx1 * vy1));
        }

        float s = 0.f;
        __half2 y0 = __float2half2_rn(0.f), y1 = y0, y2 = y0, y3 = y0;

#pragma unroll
        for (int kp = 0; kp < KPT; kp++) {
            const int src = (half << 4) + kp;
            uint32_t m   = __shfl_sync(0xffffffffu, meta, src);
            __half2 w00 = u2h(__shfl_sync(0xffffffffu, wa, src));
            __half2 w10 = u2h(__shfl_sync(0xffffffffu, wb, src));
            __half2 w01 = u2h(__shfl_sync(0xffffffffu, wc, src));
            __half2 w11 = u2h(__shfl_sync(0xffffffffu, wd, src));

            int i00 = ((bbase + (int)(m & 0x3FFFu)) << 4) + sub;
            int i10 = i00 + (int)(((m >> 14) & 1u) << 4);
            int dy  = (int)(((m >> 15) & 1u) << 11);
            int i01 = i00 + dy;
            int i11 = i10 + dy;

            uint4 c00 = xb[i00], c10 = xb[i10], c01 = xb[i01], c11 = xb[i11];
            const unsigned* p00 = &c00.x;
            const unsigned* p10 = &c10.x;
            const unsigned* p01 = &c01.x;
            const unsigned* p11 = &c11.x;

            __half2 t0, t1, t2, t3;
            t0 = __hmul2(w00, u2h(p00[0]));
            t0 = __hfma2(w10, u2h(p10[0]), t0);
            t0 = __hfma2(w01, u2h(p01[0]), t0);
            t0 = __hfma2(w11, u2h(p11[0]), t0);
            t1 = __hmul2(w00, u2h(p00[1]));
            t1 = __hfma2(w10, u2h(p10[1]), t1);
            t1 = __hfma2(w01, u2h(p01[1]), t1);
            t1 = __hfma2(w11, u2h(p11[1]), t1);
            t2 = __hmul2(w00, u2h(p00[2]));
            t2 = __hfma2(w10, u2h(p10[2]), t2);
            t2 = __hfma2(w01, u2h(p01[2]), t2);
            t2 = __hfma2(w11, u2h(p11[2]), t2);
            t3 = __hmul2(w00, u2h(p00[3]));
            t3 = __hfma2(w10, u2h(p10[3]), t3);
            t3 = __hfma2(w01, u2h(p01[3]), t3);
            t3 = __hfma2(w11, u2h(p11[3]), t3);

            __half2 dp = __hmul2(uh0, t0);
            dp = __hfma2(uh1, t1, dp);
            dp = __hfma2(uh2, t2, dp);
            dp = __hfma2(uh3, t3, dp);
            float2 f = __half22float2(dp);
            float p = f.x + f.y;
#pragma unroll
            for (int mk = 1; mk <= 8; mk <<= 1)
                p += __shfl_xor_sync(0xffffffffu, p, mk);

            float e = __expf(fminf(p, 11.f));
            s += e;
            __half2 eh = __float2half2_rn(e);
            y0 = __hfma2(eh, t0, y0);
            y1 = __hfma2(eh, t1, y1);
            y2 = __hfma2(eh, t2, y2);
            y3 = __hfma2(eh, t3, y3);
        }

        __half2 invh = __float2half2_rn(1.f / s);
        uint4 st;
        st.x = h2u(__hmul2(y0, invh));
        st.y = h2u(__hmul2(y1, invh));
        st.z = h2u(__hmul2(y2, invh));
        st.w = h2u(__hmul2(y3, invh));
        *(uint4*)(g_yh + (size_t)pix * CH + sub * 8) = st;
    }
}

// ---------------- Kernel 3: out = x + W_pv @ y~  (bounced, overlaid) --------
// smem: W_pv [0,32K) | y B-operand [32K,48K); after MMA the SAME region is
// reused as the fp32 bounce buffer Y (36.9KB) -> total 48KB, 4 CTAs/SM.
#define YST 72   // bounce stride in floats
__global__ void __launch_bounds__(256) k_gemm_o(const float* __restrict__ x,
                                                float* __restrict__ out) {
    extern __shared__ __align__(128) char sm[];
    const int tid  = threadIdx.x;
    const int lane = tid & 31, wid = tid >> 5;
    const int wm = wid & 1, wn = wid >> 1;
    const int pix0 = blockIdx.x << 6;

    const uint32_t smA = smem_u32(sm);
    const uint32_t smB = smA + 32768;

    load_tile_async<128>(g_wpvh, smA, tid);                // A: weights (32KB)
    load_tile_async<64>(g_yh + (size_t)pix0 * CH, smB, tid); // B: y (16KB)
    CP_COMMIT();
    CP_WAIT0();
    __syncthreads();

    float acc[4][2][4];
#pragma unroll
    for (int i = 0; i < 4; i++)
#pragma unroll
        for (int j = 0; j < 2; j++)
#pragma unroll
            for (int k = 0; k < 4; k++) acc[i][j][k] = 0.f;

#pragma unroll
    for (int ks = 0; ks < 8; ks++) {
        uint32_t a[4][4];
#pragma unroll
        for (int mi = 0; mi < 4; mi++) {
            int row = wm * 64 + mi * 16 + (lane & 15);
            int ch  = ks * 2 + (lane >> 4);
            ldsm_x4(smA + row * 256 + ((ch ^ (row & 7)) << 4),
                    a[mi][0], a[mi][1], a[mi][2], a[mi][3]);
        }
        uint32_t bb[4];
        {
            int row = wn * 16 + (lane & 7) + ((lane >> 4) & 1) * 8;
            int ch  = ks * 2 + ((lane >> 3) & 1);
            ldsm_x4(smB + row * 256 + ((ch ^ (row & 7)) << 4),
                    bb[0], bb[1], bb[2], bb[3]);
        }
#pragma unroll
        for (int mi = 0; mi < 4; mi++) {
            mma16816(acc[mi][0], a[mi][0], a[mi][1], a[mi][2], a[mi][3], bb[0], bb[1]);
            mma16816(acc[mi][1], a[mi][0], a[mi][1], a[mi][2], a[mi][3], bb[2], bb[3]);
        }
    }
    __syncthreads();   // operands dead -> safe to overlay bounce buffer

    // bounce fragments -> fp32 smem (overlaid on operand region)
    float* Y = (float*)sm;
#pragma unroll
    for (int mi = 0; mi < 4; mi++) {
        int o = wm * 64 + mi * 16 + (lane >> 2);
#pragma unroll
        for (int ni = 0; ni < 2; ni++) {
            int n = wn * 16 + ni * 8 + 2 * (lane & 3);
            float* d = acc[mi][ni];
            *(float2*)(Y + o * YST + n)       = make_float2(d[0], d[1]);
            *(float2*)(Y + (o + 8) * YST + n) = make_float2(d[2], d[3]);
        }
    }
    __syncthreads();

    // coalesced residual epilogue: lanes 0-15 span a full 256B row
    const int b   = pix0 >> 14;
    const int hw0 = pix0 & (HWSZ - 1);
    const int px  = (tid & 15) << 2;
#pragma unroll
    for (int j = 0; j < 8; j++) {
        int r = (tid >> 4) + 16 * j;
        float4 yv = *(const float4*)(Y + r * YST + px);
        size_t g = ((size_t)b * CH + r) * HWSZ + hw0 + px;
        float4 xv = *(const float4*)(x + g);
        *(float4*)(out + g) = make_float4(xv.x + yv.x, xv.y + yv.y,
                                          xv.z + yv.z, xv.w + yv.w);
    }
}

// ---------------- launcher ----------------
extern "C" void kernel_launch(void* const* d_in, const int* in_sizes, int n_in,
                              void* d_out, int out_size) {
    const float* x     = (const float*)d_in[0];
    const int*   psf   = (const int*)  d_in[1];
    const float* delta = (const float*)d_in[2];
    const float* wqkv  = (const float*)d_in[3];
    const float* wproj = (const float*)d_in[4];
    float* out = (float*)d_out;

    const int smem_i = 16384 + 128 * SST * 2;   // 34816 (prep tile + staging)
    const int smem_g = 49152;
    cudaFuncSetAttribute(k_init,   cudaFuncAttributeMaxDynamicSharedMemorySize, smem_i);
    cudaFuncSetAttribute(k_gemm_u, cudaFuncAttributeMaxDynamicSharedMemorySize, smem_g);
    cudaFuncSetAttribute(k_gemm_o, cudaFuncAttributeMaxDynamicSharedMemorySize, smem_g);

    k_init<<<1280, 256, smem_i>>>(x, wqkv, wproj);
    k_gemm_u<<<NPIX / 64, 256, smem_g>>>();
    k_attn<<<NPIX / 32, 256>>>(psf, delta);
    k_gemm_o<<<NPIX / 64, 256, smem_g>>>(x, out);
}

// round 17
// speedup vs baseline: 1.2260x; 1.0022x over previous
#include <cuda_runtime.h>
#include <cuda_fp16.h>
#include <cstdint>

#define BATCH 4
#define CH    128
#define HH    128
#define WW    128
#define KPT   8
#define HWSZ  (HH * WW)           // 16384
#define NPIX  (BATCH * HWSZ)      // 65536
#define RADIUS 4.0f
#define SCALE 0.08838834764831845f  // C^-0.5

// Scratch buffers (pixel-major / NHWC, fp16)
__device__ __half g_xh [NPIX * CH];   // x fp16 NHWC (gather + GEMM operand)
__device__ __half g_uh [NPIX * CH];   // u = (SCALE*GT) @ x
__device__ __half g_yh [NPIX * CH];   // y~ = sum_k attn * x~
__device__ __half g_gth [CH * CH];    // GT[d][c] * SCALE, K-contig
__device__ __half g_wpvh[CH * CH];    // W_pv[o][c], K-contig

// ---------------- helpers ----------------
__device__ __forceinline__ uint32_t smem_u32(const void* p) {
    uint32_t a;
    asm("{ .reg .u64 t; cvta.to.shared.u64 t, %1; cvt.u32.u64 %0, t; }"
        : "=r"(a) : "l"(p));
    return a;
}
__device__ __forceinline__ unsigned h2u(__half2 h) { return *reinterpret_cast<unsigned*>(&h); }
__device__ __forceinline__ __half2 u2h(unsigned u) { return *reinterpret_cast<__half2*>(&u); }

__device__ __forceinline__ void ldsm_x4(uint32_t a, uint32_t& r0, uint32_t& r1,
                                        uint32_t& r2, uint32_t& r3) {
    asm volatile("ldmatrix.sync.aligned.m8n8.x4.shared.b16 {%0,%1,%2,%3}, [%4];"
                 : "=r"(r0), "=r"(r1), "=r"(r2), "=r"(r3) : "r"(a));
}
__device__ __forceinline__ void ldsm_x4_t(uint32_t a, uint32_t& r0, uint32_t& r1,
                                          uint32_t& r2, uint32_t& r3) {
    asm volatile("ldmatrix.sync.aligned.m8n8.x4.trans.shared.b16 {%0,%1,%2,%3}, [%4];"
                 : "=r"(r0), "=r"(r1), "=r"(r2), "=r"(r3) : "r"(a));
}
__device__ __forceinline__ void mma16816(float* d, uint32_t a0, uint32_t a1,
                                         uint32_t a2, uint32_t a3,
                                         uint32_t b0, uint32_t b1) {
    asm volatile("mma.sync.aligned.m16n8k16.row.col.f32.f16.f16.f32 "
                 "{%0,%1,%2,%3},{%4,%5,%6,%7},{%8,%9},{%0,%1,%2,%3};"
                 : "+f"(d[0]), "+f"(d[1]), "+f"(d[2]), "+f"(d[3])
                 : "r"(a0), "r"(a1), "r"(a2), "r"(a3), "r"(b0), "r"(b1));
}

#define CP_COMMIT() asm volatile("cp.async.commit_group;" ::: "memory")
#define CP_WAIT0()  asm volatile("cp.async.wait_group 0;" ::: "memory")

// async copy of an Rx128 fp16 K-contig tile into XOR-swizzled smem
template <int ROWS>
__device__ __forceinline__ void load_tile_async(const __half* __restrict__ src,
                                                uint32_t dst, int tid) {
#pragma unroll
    for (int i = 0; i < ROWS / 16; i++) {
        int idx = i * 256 + tid;           // chunks of 16B
        int r   = idx >> 4;
        int c   = idx & 15;
        uint32_t s = dst + r * 256 + ((c ^ (r & 7)) << 4);
        const void* g = src + (size_t)r * 128 + c * 8;
        asm volatile("cp.async.cg.shared.global [%0], [%1], 16;"
                     :: "r"(s), "l"(g) : "memory");
    }
}

// ---------------- Kernel I: fused weight fold + (x NCHW -> xh NHWC) --------
// blocks 0..255: weight fold (scheduled first -> done early, hides under prep)
// blocks 256..1279: 64-px transpose tile (ldmatrix-trans path, 34.8KB smem)
#define SST 72   // staging stride in halfs (144B: conflict-free ldmatrix rows)
__global__ void __launch_bounds__(256) k_init(const float* __restrict__ x,
                                              const float* __restrict__ wqkv,
                                              const float* __restrict__ wproj) {
    extern __shared__ __align__(128) char sm[];
    const int blk = blockIdx.x;
    const int tid = threadIdx.x;

    if (blk >= 256) {
        const int lane = tid & 31, wid = tid >> 5;
        const int pix0 = (blk - 256) << 6;
        const int b    = pix0 >> 14;
        const int hw0  = pix0 & (HWSZ - 1);

        __half* S = (__half*)(sm + 16384);

        // Phase 1: coalesced stage x -> fp16 S[c][px]
#pragma unroll
        for (int i = 0; i < 8; i++) {
            int idx = i * 256 + tid;
            int c = idx >> 4, j4 = idx & 15;
            float4 v = *(const float4*)(x + ((size_t)b * CH + c) * HWSZ + hw0 + j4 * 4);
            *(__half2*)(S + c * SST + j4 * 4)     = __floats2half2_rn(v.x, v.y);
            *(__half2*)(S + c * SST + j4 * 4 + 2) = __floats2half2_rn(v.z, v.w);
        }
        __syncthreads();

        // Phase 1c: hardware transpose into swizzled NHWC tile at sm[0,16K)
#pragma unroll
        for (int i = 0; i < 4; i++) {
            int g  = wid + 8 * i;              // tile group 0..31
            int c0 = (g >> 3) << 5;            // 32-channel span
            int pb = g & 7;                    // px block (8 px)
            uint32_t src = smem_u32(S + (c0 + ((lane >> 3) << 3) + (lane & 7)) * SST + pb * 8);
            uint32_t r0, r1, r2, r3;
            ldsm_x4_t(src, r0, r1, r2, r3);
            int px = (pb << 3) + (lane >> 2);
            uint32_t rr[4] = {r0, r1, r2, r3};
#pragma unroll
            for (int k = 0; k < 4; k++) {
                int c2    = (c0 >> 1) + (k << 2) + (lane & 3);
                int chunk = c2 >> 2;
                int inner = (c2 & 3) << 2;
                *(uint32_t*)(sm + px * 256 + ((chunk ^ (px & 7)) << 4) + inner) = rr[k];
            }
        }
        __syncthreads();

        // Phase 1b: coalesced write of g_xh NHWC
#pragma unroll
        for (int i = 0; i < 4; i++) {
            int idx = i * 256 + tid;
            int px = idx >> 4, q = idx & 15;
            uint4 v = *(const uint4*)(sm + px * 256 + ((q ^ (px & 7)) << 4));
            *(uint4*)(g_xh + (size_t)(pix0 + px) * CH + q * 8) = v;
        }
    } else {
        // ---- weight fold ----
        float* sv  = (float*)sm;              // [128]
        float* red = sv + 128;                // [256]
        const int w  = blk;                   // 0..255
        const int c  = tid & 127;
        const int hf = tid >> 7;

        if (w < 128) {
            const int d = w;
            if (tid < CH) sv[tid] = wqkv[(128 + tid) * CH + d];   // Wk[o][d]
            __syncthreads();
            float acc = 0.f;
#pragma unroll 16
            for (int o = 0; o < 64; o++) {
                int oo = hf * 64 + o;
                acc += wqkv[oo * CH + c] * sv[oo];                // Wq[o][c]
            }
            red[tid] = acc;
            __syncthreads();
            if (tid < CH)
                g_gth[d * CH + c] = __float2half((red[tid] + red[tid + 128]) * SCALE);
        } else {
            const int o = w - 128;
            if (tid < CH) sv[tid] = wproj[o * CH + tid];
            __syncthreads();
            float acc = 0.f;
#pragma unroll 16
            for (int m = 0; m < 64; m++) {
                int mm = hf * 64 + m;
                acc += sv[mm] * wqkv[(256 + mm) * CH + c];        // Wv[m][c]
            }
            red[tid] = acc;
            __syncthreads();
            if (tid < CH) g_wpvh[o * CH + c] = __float2half(red[tid] + red[tid + 128]);
        }
    }
}

// ---------------- Kernel 1: u = xh @ (SCALE*GT)^T  (M=64px, N=128dch) ------
__global__ void __launch_bounds__(256) k_gemm_u() {
    extern __shared__ __align__(128) char sm[];
    const int tid  = threadIdx.x;
    const int lane = tid & 31, wid = tid >> 5;
    const int wm = wid & 1, wn = wid >> 1;
    const int pix0 = blockIdx.x << 6;

    const uint32_t smA = smem_u32(sm);
    const uint32_t smB = smA + 16384;

    load_tile_async<64>(g_xh + (size_t)pix0 * CH, smA, tid);   // A: 16KB
    load_tile_async<128>(g_gth, smB, tid);                     // B: 32KB
    CP_COMMIT();
    CP_WAIT0();
    __syncthreads();

    float acc[2][4][4];
#pragma unroll
    for (int i = 0; i < 2; i++)
#pragma unroll
        for (int j = 0; j < 4; j++)
#pragma unroll
            for (int k = 0; k < 4; k++) acc[i][j][k] = 0.f;

#pragma unroll
    for (int ks = 0; ks < 8; ks++) {
        uint32_t a[2][4];
#pragma unroll
        for (int mi = 0; mi < 2; mi++) {
            int row = wm * 32 + mi * 16 + (lane & 15);
            int ch  = ks * 2 + (lane >> 4);
            ldsm_x4(smA + row * 256 + ((ch ^ (row & 7)) << 4),
                    a[mi][0], a[mi][1], a[mi][2], a[mi][3]);
        }
        uint32_t bb[2][4];
#pragma unroll
        for (int nj = 0; nj < 2; nj++) {
            int row = wn * 32 + nj * 16 + (lane & 7) + ((lane >> 4) & 1) * 8;
            int ch  = ks * 2 + ((lane >> 3) & 1);
            ldsm_x4(smB + row * 256 + ((ch ^ (row & 7)) << 4),
                    bb[nj][0], bb[nj][1], bb[nj][2], bb[nj][3]);
        }
#pragma unroll
        for (int mi = 0; mi < 2; mi++)
#pragma unroll
            for (int nj = 0; nj < 2; nj++) {
                mma16816(acc[mi][2 * nj],     a[mi][0], a[mi][1], a[mi][2], a[mi][3],
                         bb[nj][0], bb[nj][1]);
                mma16816(acc[mi][2 * nj + 1], a[mi][0], a[mi][1], a[mi][2], a[mi][3],
                         bb[nj][2], bb[nj][3]);
            }
    }

#pragma unroll
    for (int mi = 0; mi < 2; mi++) {
        int px = pix0 + wm * 32 + mi * 16 + (lane >> 2);
#pragma unroll
        for (int ni = 0; ni < 4; ni++) {
            int dch = wn * 32 + ni * 8 + 2 * (lane & 3);
            float* d = acc[mi][ni];
            *(__half2*)(g_uh + (size_t)px * CH + dch)       = __floats2half2_rn(d[0], d[1]);
            *(__half2*)(g_uh + (size_t)(px + 8) * CH + dch) = __floats2half2_rn(d[2], d[3]);
        }
    }
}

// ---------------- Kernel 2: sampling + attention (online, max-free) ---------
// Loads-first ordering: all meta broadcasts hoisted; per point the 4 gather
// loads issue BEFORE the weight shfls so load latency overlaps them.
__global__ void __launch_bounds__(256, 3) k_attn(const int*   __restrict__ psf,
                                                 const float* __restrict__ delta) {
    const int tid  = threadIdx.x;
    const int lane = tid & 31;
    const int wid  = tid >> 5;
    const int half = lane >> 4;
    const int sub  = lane & 15;

    const int pix0  = blockIdx.x << 5;
    const int bbase = (pix0 >> 14) << 14;

    float dval = 0.f;
    if (lane < 16) dval = tanhf(delta[lane]) * RADIUS;
    const float dxv = __shfl_sync(0xffffffffu, dval, (sub & 7) * 2);
    const float dyv = __shfl_sync(0xffffffffu, dval, (sub & 7) * 2 + 1);

    const uint4* xb = (const uint4*)g_xh;
    const int2*  pb = (const int2*)psf;

#pragma unroll
    for (int it = 0; it < 2; it++) {
        const int pix = pix0 + (wid << 2) + (it << 1) + half;

        uint4 up = ((const uint4*)g_uh)[(size_t)pix * 16 + sub];
        __half2 uh0 = u2h(up.x), uh1 = u2h(up.y), uh2 = u2h(up.z), uh3 = u2h(up.w);

        uint32_t meta = 0, wa = 0, wb = 0, wc = 0, wd = 0;
        if (sub < 8) {
            int2 anc = pb[(size_t)pix * KPT + sub];
            float ix = (float)anc.x + dxv;
            float iy = (float)anc.y + dyv;
            float x0f = floorf(ix), y0f = floorf(iy);
            float wx1 = ix - x0f,  wy1 = iy - y0f;
            float wx0 = 1.f - wx1, wy0 = 1.f - wy1;
            int x0 = (int)x0f, y0 = (int)y0f;
            int x1 = x0 + 1,   y1 = y0 + 1;
            float vx0 = (x0 >= 0 && x0 <= WW - 1) ? 1.f : 0.f;
            float vx1 = (x1 >= 0 && x1 <= WW - 1) ? 1.f : 0.f;
            float vy0 = (y0 >= 0 && y0 <= HH - 1) ? 1.f : 0.f;
            float vy1 = (y1 >= 0 && y1 <= HH - 1) ? 1.f : 0.f;
            int cx0 = min(max(x0, 0), WW - 1);
            int cx1 = min(max(x1, 0), WW - 1);
            int cy0 = min(max(y0, 0), HH - 1);
            int cy1 = min(max(y1, 0), HH - 1);
            meta = (uint32_t)((cy0 << 7) + cx0)
                 | ((uint32_t)(cx1 - cx0) << 14)
                 | ((uint32_t)(cy1 - cy0) << 15);
            wa = h2u(__float2half2_rn(wx0 * wy0 * vx0 * vy0));
            wb = h2u(__float2half2_rn(wx1 * wy0 * vx1 * vy0));
            wc = h2u(__float2half2_rn(wx0 * wy1 * vx0 * vy1));
            wd = h2u(__float2half2_rn(wx1 * wy1 * vx1 * vy1));
        }

        // hoist the meta broadcasts for all 8 points
        uint32_t mAll[KPT];
#pragma unroll
        for (int kp = 0; kp < KPT; kp++)
            mAll[kp] = __shfl_sync(0xffffffffu, meta, (half << 4) + kp);

        float s = 0.f;
        __half2 y0 = __float2half2_rn(0.f), y1 = y0, y2 = y0, y3 = y0;

#pragma unroll
        for (int kp = 0; kp < KPT; kp++) {
            const uint32_t m = mAll[kp];
            int i00 = ((bbase + (int)(m & 0x3FFFu)) << 4) + sub;
            int i10 = i00 + (int)(((m >> 14) & 1u) << 4);
            int dy  = (int)(((m >> 15) & 1u) << 11);
            int i01 = i00 + dy;
            int i11 = i10 + dy;

            // issue the gathers first; weight shfls overlap their latency
            uint4 c00 = xb[i00], c10 = xb[i10], c01 = xb[i01], c11 = xb[i11];

            const int src = (half << 4) + kp;
            __half2 w00 = u2h(__shfl_sync(0xffffffffu, wa, src));
            __half2 w10 = u2h(__shfl_sync(0xffffffffu, wb, src));
            __half2 w01 = u2h(__shfl_sync(0xffffffffu, wc, src));
            __half2 w11 = u2h(__shfl_sync(0xffffffffu, wd, src));

            const unsigned* p00 = &c00.x;
            const unsigned* p10 = &c10.x;
            const unsigned* p01 = &c01.x;
            const unsigned* p11 = &c11.x;

            __half2 t0, t1, t2, t3;
            t0 = __hmul2(w00, u2h(p00[0]));
            t0 = __hfma2(w10, u2h(p10[0]), t0);
            t0 = __hfma2(w01, u2h(p01[0]), t0);
            t0 = __hfma2(w11, u2h(p11[0]), t0);
            t1 = __hmul2(w00, u2h(p00[1]));
            t1 = __hfma2(w10, u2h(p10[1]), t1);
            t1 = __hfma2(w01, u2h(p01[1]), t1);
            t1 = __hfma2(w11, u2h(p11[1]), t1);
            t2 = __hmul2(w00, u2h(p00[2]));
            t2 = __hfma2(w10, u2h(p10[2]), t2);
            t2 = __hfma2(w01, u2h(p01[2]), t2);
            t2 = __hfma2(w11, u2h(p11[2]), t2);
            t3 = __hmul2(w00, u2h(p00[3]));
            t3 = __hfma2(w10, u2h(p10[3]), t3);
            t3 = __hfma2(w01, u2h(p01[3]), t3);
            t3 = __hfma2(w11, u2h(p11[3]), t3);

            __half2 dp = __hmul2(uh0, t0);
            dp = __hfma2(uh1, t1, dp);
            dp = __hfma2(uh2, t2, dp);
            dp = __hfma2(uh3, t3, dp);
            float2 f = __half22float2(dp);
            float p = f.x + f.y;
#pragma unroll
            for (int mk = 1; mk <= 8; mk <<= 1)
                p += __shfl_xor_sync(0xffffffffu, p, mk);

            float e = __expf(fminf(p, 11.f));
            s += e;
            __half2 eh = __float2half2_rn(e);
            y0 = __hfma2(eh, t0, y0);
            y1 = __hfma2(eh, t1, y1);
            y2 = __hfma2(eh, t2, y2);
            y3 = __hfma2(eh, t3, y3);
        }

        __half2 invh = __float2half2_rn(1.f / s);
        uint4 st;
        st.x = h2u(__hmul2(y0, invh));
        st.y = h2u(__hmul2(y1, invh));
        st.z = h2u(__hmul2(y2, invh));
        st.w = h2u(__hmul2(y3, invh));
        *(uint4*)(g_yh + (size_t)pix * CH + sub * 8) = st;
    }
}

// ---------------- Kernel 3: out = x + W_pv @ y~  (bounced, overlaid) --------
#define YST 72   // bounce stride in floats
__global__ void __launch_bounds__(256) k_gemm_o(const float* __restrict__ x,
                                                float* __restrict__ out) {
    extern __shared__ __align__(128) char sm[];
    const int tid  = threadIdx.x;
    const int lane = tid & 31, wid = tid >> 5;
    const int wm = wid & 1, wn = wid >> 1;
    const int pix0 = blockIdx.x << 6;

    const uint32_t smA = smem_u32(sm);
    const uint32_t smB = smA + 32768;

    load_tile_async<128>(g_wpvh, smA, tid);                // A: weights (32KB)
    load_tile_async<64>(g_yh + (size_t)pix0 * CH, smB, tid); // B: y (16KB)
    CP_COMMIT();
    CP_WAIT0();
    __syncthreads();

    float acc[4][2][4];
#pragma unroll
    for (int i = 0; i < 4; i++)
#pragma unroll
        for (int j = 0; j < 2; j++)
#pragma unroll
            for (int k = 0; k < 4; k++) acc[i][j][k] = 0.f;

#pragma unroll
    for (int ks = 0; ks < 8; ks++) {
        uint32_t a[4][4];
#pragma unroll
        for (int mi = 0; mi < 4; mi++) {
            int row = wm * 64 + mi * 16 + (lane & 15);
            int ch  = ks * 2 + (lane >> 4);
            ldsm_x4(smA + row * 256 + ((ch ^ (row & 7)) << 4),
                    a[mi][0], a[mi][1], a[mi][2], a[mi][3]);
        }
        uint32_t bb[4];
        {
            int row = wn * 16 + (lane & 7) + ((lane >> 4) & 1) * 8;
            int ch  = ks * 2 + ((lane >> 3) & 1);
            ldsm_x4(smB + row * 256 + ((ch ^ (row & 7)) << 4),
                    bb[0], bb[1], bb[2], bb[3]);
        }
#pragma unroll
        for (int mi = 0; mi < 4; mi++) {
            mma16816(acc[mi][0], a[mi][0], a[mi][1], a[mi][2], a[mi][3], bb[0], bb[1]);
            mma16816(acc[mi][1], a[mi][0], a[mi][1], a[mi][2], a[mi][3], bb[2], bb[3]);
        }
    }
    __syncthreads();   // operands dead -> safe to overlay bounce buffer

    // bounce fragments -> fp32 smem (overlaid on operand region)
    float* Y = (float*)sm;
#pragma unroll
    for (int mi = 0; mi < 4; mi++) {
        int o = wm * 64 + mi * 16 + (lane >> 2);
#pragma unroll
        for (int ni = 0; ni < 2; ni++) {
            int n = wn * 16 + ni * 8 + 2 * (lane & 3);
            float* d = acc[mi][ni];
            *(float2*)(Y + o * YST + n)       = make_float2(d[0], d[1]);
            *(float2*)(Y + (o + 8) * YST + n) = make_float2(d[2], d[3]);
        }
    }
    __syncthreads();

    // coalesced residual epilogue: lanes 0-15 span a full 256B row
    const int b   = pix0 >> 14;
    const int hw0 = pix0 & (HWSZ - 1);
    const int px  = (tid & 15) << 2;
#pragma unroll
    for (int j = 0; j < 8; j++) {
        int r = (tid >> 4) + 16 * j;
        float4 yv = *(const float4*)(Y + r * YST + px);
        size_t g = ((size_t)b * CH + r) * HWSZ + hw0 + px;
        float4 xv = *(const float4*)(x + g);
        *(float4*)(out + g) = make_float4(xv.x + yv.x, xv.y + yv.y,
                                          xv.z + yv.z, xv.w + yv.w);
    }
}

// ---------------- launcher ----------------
extern "C" void kernel_launch(void* const* d_in, const int* in_sizes, int n_in,
                              void* d_out, int out_size) {
    const float* x     = (const float*)d_in[0];
    const int*   psf   = (const int*)  d_in[1];
    const float* delta = (const float*)d_in[2];
    const float* wqkv  = (const float*)d_in[3];
    const float* wproj = (const float*)d_in[4];
    float* out = (float*)d_out;

    const int smem_i = 16384 + 128 * SST * 2;   // 34816 (prep tile + staging)
    const int smem_g = 49152;
    cudaFuncSetAttribute(k_init,   cudaFuncAttributeMaxDynamicSharedMemorySize, smem_i);
    cudaFuncSetAttribute(k_gemm_u, cudaFuncAttributeMaxDynamicSharedMemorySize, smem_g);
    cudaFuncSetAttribute(k_gemm_o, cudaFuncAttributeMaxDynamicSharedMemorySize, smem_g);

    k_init<<<1280, 256, smem_i>>>(x, wqkv, wproj);
    k_gemm_u<<<NPIX / 64, 256, smem_g>>>();
    k_attn<<<NPIX / 32, 256>>>(psf, delta);
    k_gemm_o<<<NPIX / 64, 256, smem_g>>>(x, out);
}